// round 10
// baseline (speedup 1.0000x reference)
#include <cuda_runtime.h>
#include <cstdint>

// x: (8, 256, 256, 32) fp32, reflect-pad 3x3 patch extraction.
// out[b,h,w, c*9 + i] = x[b, reflect(h + i/3 - 1), reflect(w + i%3 - 1), c]
//
// Best-measured configuration (R7, 97.7us kernel) + 32-bit hoisted
// addressing (R8's alu trim):
//   Warp = 4-pixel strip along W:
//   - 18 coalesced 128B line loads (3 rows x 6 cols, lane = channel)
//   - register->smem scatter into final output order (stride-9 word scatter
//     is a permutation mod 32 banks -> conflict-free)
//   - EARLY DRAIN: as soon as pixel p's 288 words are scattered, lane 0
//     issues a 1152B cp.async.bulk for that pixel (4 pipelined bursts/warp,
//     one commit + wait at warp end).
//
// Status: DRAM-write-bound at ~6.2 TB/s (~78% of spec) — the measured
// plateau across six structurally different store mechanisms. Traffic is at
// its floor (604MB mandatory output + ~8MB input); all SM-side pipes slack.

static constexpr int B = 8;
static constexpr int H = 256;
static constexpr int W = 256;
static constexpr int C = 32;
static constexpr int TAPS = 9;
static constexpr int OUT_PER_PIX = C * TAPS;             // 288 floats = 1152 B
static constexpr int PIX_PER_WARP = 4;
static constexpr int WARPS_PER_BLOCK = 8;
static constexpr int THREADS = WARPS_PER_BLOCK * 32;     // 256
static constexpr int PIX_PER_BLOCK = PIX_PER_WARP * WARPS_PER_BLOCK;   // 32
static constexpr int BYTES_PER_PIX = OUT_PER_PIX * 4;    // 1152

__device__ __forceinline__ uint32_t smem_u32(const void* p) {
    uint32_t a;
    asm("{ .reg .u64 t; cvta.to.shared.u64 t, %1; cvt.u32.u64 %0, t; }"
        : "=r"(a) : "l"(p));
    return a;
}

__global__ __launch_bounds__(THREADS)
void patch_extract_kernel(const float* __restrict__ x, float* __restrict__ out) {
    const int warp = threadIdx.x >> 5;
    const int lane = threadIdx.x & 31;

    // blockIdx.y = b*H + h (2048 rows); blockIdx.x = 32-pixel group (8 per row)
    const int h = blockIdx.y & (H - 1);
    const int w0 = (blockIdx.x * WARPS_PER_BLOCK + warp) * PIX_PER_WARP;

    __shared__ __align__(16) float sm[WARPS_PER_BLOCK][PIX_PER_WARP * OUT_PER_PIX];
    float* s = sm[warp];

    // Reflected rows (3) and columns (6: w0-1 .. w0+4). PAD=1: -1 -> 1, N -> N-2.
    int rh[3];
#pragma unroll
    for (int d = 0; d < 3; d++) {
        int r = h + d - 1;
        rh[d] = (r < 0) ? 1 : ((r >= H) ? H - 2 : r);
    }
    // Precompute 32-bit column byte-ish offsets (elements) once.
    uint32_t rwc[6];
#pragma unroll
    for (int t = 0; t < 6; t++) {
        int cc = w0 - 1 + t;
        cc = (cc < 0) ? 1 : ((cc >= W) ? W - 2 : cc);
        rwc[t] = (uint32_t)cc * C;
    }

    // 32-bit addressing within a batch image (8 MiB).
    const float* xb = x + ((uint32_t)(blockIdx.y >> 8)) * (uint32_t)(H * W * C);

    // 18 independent, fully-coalesced 128B line loads (lane = channel).
    float v[3][6];
#pragma unroll
    for (int dr = 0; dr < 3; dr++) {
        const float* rp = xb + (uint32_t)rh[dr] * (uint32_t)(W * C) + lane;
#pragma unroll
        for (int t = 0; t < 6; t++) {
            v[dr][t] = rp[rwc[t]];
        }
    }

    // Destination for this warp's 4 contiguous pixels.
    const size_t pix0 = (size_t)blockIdx.y * W + w0;
    float* gdst = out + pix0 * OUT_PER_PIX;
    const uint32_t sbase = smem_u32(s);
    const int lb = lane * TAPS;

    // Per pixel: scatter 9 words in output order, then immediately hand the
    // 1152B block to the TMA store engine while the next pixel scatters.
#pragma unroll
    for (int p = 0; p < PIX_PER_WARP; p++) {
#pragma unroll
        for (int dr = 0; dr < 3; dr++) {
#pragma unroll
            for (int dj = 0; dj < 3; dj++) {
                s[p * OUT_PER_PIX + lb + dr * 3 + dj] = v[dr][p + dj];
            }
        }
        __syncwarp();
        if (lane == 0) {
            asm volatile("fence.proxy.async.shared::cta;" ::: "memory");
            asm volatile(
                "cp.async.bulk.global.shared::cta.bulk_group [%0], [%1], %2;"
                :: "l"(gdst + (uint32_t)p * OUT_PER_PIX),
                   "r"(sbase + (uint32_t)(p * BYTES_PER_PIX)),
                   "r"((uint32_t)BYTES_PER_PIX)
                : "memory");
        }
    }

    if (lane == 0) {
        asm volatile("cp.async.bulk.commit_group;" ::: "memory");
        // smem must stay live until the bulk copies' smem reads complete.
        asm volatile("cp.async.bulk.wait_group 0;" ::: "memory");
    }
    __syncwarp();
}

extern "C" void kernel_launch(void* const* d_in, const int* in_sizes, int n_in,
                              void* d_out, int out_size) {
    const float* x = (const float*)d_in[0];
    float* out = (float*)d_out;
    (void)in_sizes; (void)n_in; (void)out_size;

    dim3 grid(W / PIX_PER_BLOCK, B * H);   // (8, 2048)
    patch_extract_kernel<<<grid, THREADS>>>(x, out);
}

// round 11
// speedup vs baseline: 1.0079x; 1.0079x over previous
#include <cuda_runtime.h>
#include <cstdint>

// x: (8, 256, 256, 32) fp32, reflect-pad 3x3 patch extraction.
// out[b,h,w, c*9 + i] = x[b, reflect(h + i/3 - 1), reflect(w + i%3 - 1), c]
//
// FINAL: best-measured configuration (R7, 97.7us kernel — ~99.5% of the
// achieved HBM write-bandwidth bound) + L2 evict-first policy on the output
// stream so the 64MiB input keeps its L2 residency for the 9x tap reuse.
//
//   Warp = 4-pixel strip along W:
//   - 18 coalesced 128B line loads (3 rows x 6 cols, lane = channel)
//   - register->smem scatter into final output order (stride-9 word scatter
//     is a permutation mod 32 banks -> conflict-free)
//   - EARLY DRAIN: as soon as pixel p's 288 words are scattered, lane 0
//     issues a 1152B cp.async.bulk (evict-first) for that pixel; 4
//     pipelined bursts/warp, one commit + wait at warp end.
//
// Roofline status: DRAM-write-bound. 604MB mandatory output / 6.22TB/s
// achieved = 97.2us floor; kernel measures 97.7us. Seven structurally
// different store mechanisms all plateau at 77.7-79.0% DRAM; all SM-side
// pipes slack. No software lever changes mandatory traffic.

static constexpr int B = 8;
static constexpr int H = 256;
static constexpr int W = 256;
static constexpr int C = 32;
static constexpr int TAPS = 9;
static constexpr int OUT_PER_PIX = C * TAPS;             // 288 floats = 1152 B
static constexpr int PIX_PER_WARP = 4;
static constexpr int WARPS_PER_BLOCK = 8;
static constexpr int THREADS = WARPS_PER_BLOCK * 32;     // 256
static constexpr int PIX_PER_BLOCK = PIX_PER_WARP * WARPS_PER_BLOCK;   // 32
static constexpr int BYTES_PER_PIX = OUT_PER_PIX * 4;    // 1152

__device__ __forceinline__ uint32_t smem_u32(const void* p) {
    uint32_t a;
    asm("{ .reg .u64 t; cvta.to.shared.u64 t, %1; cvt.u32.u64 %0, t; }"
        : "=r"(a) : "l"(p));
    return a;
}

__global__ __launch_bounds__(THREADS)
void patch_extract_kernel(const float* __restrict__ x, float* __restrict__ out) {
    const int warp = threadIdx.x >> 5;
    const int lane = threadIdx.x & 31;

    // blockIdx.y = b*H + h (2048 rows); blockIdx.x = 32-pixel group (8 per row)
    const int h = blockIdx.y & (H - 1);
    const int w0 = (blockIdx.x * WARPS_PER_BLOCK + warp) * PIX_PER_WARP;

    __shared__ __align__(16) float sm[WARPS_PER_BLOCK][PIX_PER_WARP * OUT_PER_PIX];
    float* s = sm[warp];

    // Reflected rows (3) and columns (6: w0-1 .. w0+4). PAD=1: -1 -> 1, N -> N-2.
    int rh[3];
#pragma unroll
    for (int d = 0; d < 3; d++) {
        int r = h + d - 1;
        rh[d] = (r < 0) ? 1 : ((r >= H) ? H - 2 : r);
    }
    int rw[6];
#pragma unroll
    for (int t = 0; t < 6; t++) {
        int cc = w0 - 1 + t;
        rw[t] = (cc < 0) ? 1 : ((cc >= W) ? W - 2 : cc);
    }

    // 32-bit addressing within a batch image (8 MiB).
    const float* xb = x + ((uint32_t)(blockIdx.y >> 8)) * (uint32_t)(H * W * C);

    // 18 independent, fully-coalesced 128B line loads (lane = channel).
    float v[3][6];
#pragma unroll
    for (int dr = 0; dr < 3; dr++) {
        const float* rp = xb + (uint32_t)rh[dr] * (uint32_t)(W * C) + lane;
#pragma unroll
        for (int t = 0; t < 6; t++) {
            v[dr][t] = rp[(uint32_t)rw[t] * C];
        }
    }

    // Destination for this warp's 4 contiguous pixels.
    const size_t pix0 = (size_t)blockIdx.y * W + w0;
    float* gdst = out + pix0 * OUT_PER_PIX;
    const uint32_t sbase = smem_u32(s);
    const int lb = lane * TAPS;

    // Evict-first policy for the write-once output stream.
    uint64_t policy;
    asm("createpolicy.fractional.L2::evict_first.b64 %0, 1.0;" : "=l"(policy));

    // Per pixel: scatter 9 words in output order, then immediately hand the
    // 1152B block to the TMA store engine while the next pixel scatters.
#pragma unroll
    for (int p = 0; p < PIX_PER_WARP; p++) {
#pragma unroll
        for (int dr = 0; dr < 3; dr++) {
#pragma unroll
            for (int dj = 0; dj < 3; dj++) {
                s[p * OUT_PER_PIX + lb + dr * 3 + dj] = v[dr][p + dj];
            }
        }
        __syncwarp();
        if (lane == 0) {
            asm volatile("fence.proxy.async.shared::cta;" ::: "memory");
            asm volatile(
                "cp.async.bulk.global.shared::cta.bulk_group.L2::cache_hint "
                "[%0], [%1], %2, %3;"
                :: "l"(gdst + (uint32_t)p * OUT_PER_PIX),
                   "r"(sbase + (uint32_t)(p * BYTES_PER_PIX)),
                   "r"((uint32_t)BYTES_PER_PIX),
                   "l"(policy)
                : "memory");
        }
    }

    if (lane == 0) {
        asm volatile("cp.async.bulk.commit_group;" ::: "memory");
        // smem must stay live until the bulk copies' smem reads complete.
        asm volatile("cp.async.bulk.wait_group 0;" ::: "memory");
    }
    __syncwarp();
}

extern "C" void kernel_launch(void* const* d_in, const int* in_sizes, int n_in,
                              void* d_out, int out_size) {
    const float* x = (const float*)d_in[0];
    float* out = (float*)d_out;
    (void)in_sizes; (void)n_in; (void)out_size;

    dim3 grid(W / PIX_PER_BLOCK, B * H);   // (8, 2048)
    patch_extract_kernel<<<grid, THREADS>>>(x, out);
}